// round 15
// baseline (speedup 1.0000x reference)
#include <cuda_runtime.h>
#include <cstdint>

// Problem constants
constexpr int BB = 8;
constexpr int NN = 1024;
constexpr int CC = 768;
constexpr int HH = 12;
constexpr int DD = 64;
constexpr float QSCALE = 0.125f;                  // HEAD_DIM^-0.5
constexpr float LOG2E  = 1.4426950408889634f;     // folded into Q scale

// Scratch (allocation-free rule: __device__ globals)
__device__ float g_q[BB * HH * NN * DD];   // [B,H,N,D] tf32, scaled by 0.125*log2e
__device__ float g_k[BB * HH * NN * DD];   // [B,H,N,D] tf32
__device__ float g_v[BB * HH * NN * DD];   // [B,H,D,N] (TRANSPOSED) tf32
__device__ float g_ao[BB * NN * CC];       // tf32-rounded attention output
__device__ float g_xc[8192 * 768];         // tf32-rounded x
__device__ float g_wqc[2304 * 768];        // tf32-rounded w_qkv
__device__ float g_wpc[768 * 768];         // tf32-rounded w_proj

// ---------------------------------------------------------------------------
// helpers (portable PTX only — harness compiles at sm_103 (no 'a'))
// ---------------------------------------------------------------------------
__device__ __forceinline__ uint32_t smem_u32(const void* p) {
    uint32_t a;
    asm("{ .reg .u64 t; cvta.to.shared.u64 t, %1; cvt.u32.u64 %0, t; }" : "=r"(a) : "l"(p));
    return a;
}
__device__ __forceinline__ float f2tf(float x) {
    uint32_t u;
    asm("cvt.rna.tf32.f32 %0, %1;" : "=r"(u) : "f"(x));
    return __uint_as_float(u);
}
__device__ __forceinline__ void mma8(float c[4], const uint32_t a[4], const uint32_t b[2]) {
    asm volatile(
        "mma.sync.aligned.m16n8k8.row.col.f32.tf32.tf32.f32 "
        "{%0,%1,%2,%3},{%4,%5,%6,%7},{%8,%9},{%0,%1,%2,%3};\n"
        : "+f"(c[0]), "+f"(c[1]), "+f"(c[2]), "+f"(c[3])
        : "r"(a[0]), "r"(a[1]), "r"(a[2]), "r"(a[3]), "r"(b[0]), "r"(b[1]));
}
__device__ __forceinline__ void ldsm4(uint32_t& r0, uint32_t& r1, uint32_t& r2,
                                      uint32_t& r3, uint32_t addr) {
    asm volatile("ldmatrix.sync.aligned.m8n8.x4.shared.b16 {%0,%1,%2,%3}, [%4];"
                 : "=r"(r0), "=r"(r1), "=r"(r2), "=r"(r3) : "r"(addr));
}
__device__ __forceinline__ void cp16(uint32_t dst, const void* src) {
    asm volatile("cp.async.cg.shared.global [%0], [%1], 16;" :: "r"(dst), "l"(src));
}
__device__ __forceinline__ void cp_commit() {
    asm volatile("cp.async.commit_group;" ::: "memory");
}
template <int N> __device__ __forceinline__ void cp_wait_group() {
    asm volatile("cp.async.wait_group %0;" :: "n"(N) : "memory");
}

// ---------------------------------------------------------------------------
// fused fp32 -> tf32 rounding of x, w_qkv, w_proj (one launch)
// ---------------------------------------------------------------------------
constexpr int N4_X  = 8192 * 768 / 4;
constexpr int N4_WQ = 2304 * 768 / 4;
constexpr int N4_WP = 768 * 768 / 4;

__global__ __launch_bounds__(256) void cvt_all(
    const float4* __restrict__ x, const float4* __restrict__ wq,
    const float4* __restrict__ wp)
{
    const int i = blockIdx.x * 256 + threadIdx.x;
    const float4* src;
    float4* dst;
    int j = i;
    if (j < N4_X) { src = x; dst = (float4*)g_xc; }
    else if ((j -= N4_X) < N4_WQ) { src = wq; dst = (float4*)g_wqc; }
    else if ((j -= N4_WQ) < N4_WP) { src = wp; dst = (float4*)g_wpc; }
    else return;
    float4 v = src[j];
    dst[j] = make_float4(f2tf(v.x), f2tf(v.y), f2tf(v.z), f2tf(v.w));
}

// ---------------------------------------------------------------------------
// QKV GEMM (gemm0): C[m,n] = sum_k x[m,k]*wqkv[n,k], K=768.
// Block tile 128x128, 128 threads (4 warps 2x2), warp tile 64x64, BK=32,
// cp.async double-buffered, ldmatrix fragments, 3 CTAs/SM.
// Epilogue: q/k row-major (32B-sector aligned); V staged through smem
// transpose -> fully coalesced [B,H,D,N] stores (fixes 8x sector waste).
// ---------------------------------------------------------------------------
constexpr int GEMM_SMEM_BYTES = 4 * 128 * 36 * 4;   // 73728 (>= 128*132*4 too)

__global__ __launch_bounds__(128, 3) void gemm0_tc()
{
    extern __shared__ float smem[];

    const int tid  = threadIdx.x;
    const int lane = tid & 31;
    const int warp = tid >> 5;
    const int g  = lane >> 2;
    const int tg = lane & 3;
    const int lb = lane >> 3;
    const int lr = lane & 7;
    const int wm = warp >> 1;
    const int wn = warp & 1;
    const int row0 = blockIdx.y * 128;
    const int col0 = blockIdx.x * 128;

    const uint32_t abase0 = smem_u32(smem);
    const uint32_t bbase0 = abase0 + 2 * 128 * 36 * 4;

    const uint32_t aoff = (uint32_t)(((wm * 64 + (lb & 1) * 8 + lr) * 36 + (lb >> 1) * 4) * 4);
    const uint32_t boff = (uint32_t)(((wn * 64 + (lb >> 1) * 8 + lr) * 36 + (lb & 1) * 4) * 4);

    float c[4][8][4];
#pragma unroll
    for (int mi = 0; mi < 4; ++mi)
#pragma unroll
        for (int ni = 0; ni < 8; ++ni)
#pragma unroll
            for (int r = 0; r < 4; ++r) c[mi][ni][r] = 0.f;

    auto load_slab = [&](int slab, int buf) {
        const int k0 = slab * 32;
        const uint32_t ab = abase0 + buf * (128 * 36 * 4);
        const uint32_t bb = bbase0 + buf * (128 * 36 * 4);
#pragma unroll
        for (int j = 0; j < 16; ++j) {
            const int id = j * 128 + tid;
            const int isB = id >> 10;
            const int cid = id & 1023;
            const int row = cid >> 3;
            const int cc = cid & 7;
            const float* src = (isB ? g_wqc : g_xc)
                + (size_t)((isB ? col0 : row0) + row) * 768 + k0 + cc * 4;
            const uint32_t dst = (isB ? bb : ab) + row * 144 + cc * 16;
            cp16(dst, src);
        }
        cp_commit();
    };

    load_slab(0, 0);

    for (int i = 0; i < 24; ++i) {
        const int cur = i & 1;
        cp_wait_group<0>();
        __syncthreads();

        const uint32_t ab = abase0 + cur * (128 * 36 * 4) + aoff;
        const uint32_t bb = bbase0 + cur * (128 * 36 * 4) + boff;

        auto do_ks = [&](int ks) {
            const uint32_t kkb = ks * 32;
            uint32_t a[4][4];
#pragma unroll
            for (int mi = 0; mi < 4; ++mi)
                ldsm4(a[mi][0], a[mi][1], a[mi][2], a[mi][3],
                      ab + mi * (16 * 144) + kkb);
            uint32_t b[8][2];
#pragma unroll
            for (int ni2 = 0; ni2 < 4; ++ni2)
                ldsm4(b[2 * ni2][0], b[2 * ni2][1], b[2 * ni2 + 1][0], b[2 * ni2 + 1][1],
                      bb + ni2 * (16 * 144) + kkb);
#pragma unroll
            for (int mi = 0; mi < 4; ++mi)
#pragma unroll
                for (int ni = 0; ni < 8; ++ni)
                    mma8(c[mi][ni], a[mi], b[ni]);
        };

        do_ks(0);
        if (i + 1 < 24) load_slab(i + 1, cur ^ 1);
        do_ks(1); do_ks(2); do_ks(3);
    }

    const int s = col0 / 768;                       // 0=q,1=k,2=v
    if (s == 2) {
        // ---- V: stage transposed tile in smem, coalesced [d][n] stores ----
        const int colr = col0 - 1536;
        __syncthreads();                            // pipeline smem now free
#pragma unroll
        for (int mi = 0; mi < 4; ++mi) {
            const int r = wm * 64 + mi * 16 + g;    // local row
#pragma unroll
            for (int ni = 0; ni < 8; ++ni) {
                const int o = wn * 64 + ni * 8 + 2 * tg;   // local col (d)
                smem[o * 132 + r]           = f2tf(c[mi][ni][0]);
                smem[(o + 1) * 132 + r]     = f2tf(c[mi][ni][1]);
                smem[o * 132 + r + 8]       = f2tf(c[mi][ni][2]);
                smem[(o + 1) * 132 + r + 8] = f2tf(c[mi][ni][3]);
            }
        }
        __syncthreads();
        const int b = row0 >> 10, nbase = row0 & 1023;
#pragma unroll
        for (int j = 0; j < 32; ++j) {
            const int dloc = warp * 32 + j;
            const int dg = colr + dloc;
            const int h = dg >> 6, d = dg & 63;
            float* dst = g_v + (((size_t)b * HH + h) * DD + d) * NN + nbase;
#pragma unroll
            for (int k = 0; k < 4; ++k)
                dst[k * 32 + lane] = smem[dloc * 132 + k * 32 + lane];
        }
    } else {
        float* dstb = (s == 0) ? g_q : g_k;
        const float mul = (s == 0) ? QSCALE * LOG2E : 1.0f;
        const int colr = col0 - s * 768;
#pragma unroll
        for (int mi = 0; mi < 4; ++mi) {
            const int r = row0 + wm * 64 + mi * 16 + g;
            const int b = r >> 10, n0 = r & 1023, n1 = (r + 8) & 1023;
#pragma unroll
            for (int ni = 0; ni < 8; ++ni) {
                const int o = colr + wn * 64 + ni * 8 + 2 * tg;
                const int h = o >> 6, d = o & 63;
                const size_t base = ((size_t)b * HH + h) * NN;
                *(float2*)(dstb + (base + n0) * DD + d) =
                    make_float2(f2tf(c[mi][ni][0] * mul), f2tf(c[mi][ni][1] * mul));
                *(float2*)(dstb + (base + n1) * DD + d) =
                    make_float2(f2tf(c[mi][ni][2] * mul), f2tf(c[mi][ni][3] * mul));
            }
        }
    }
}

// ---------------------------------------------------------------------------
// Output projection (gemm1): C[m,n] = sum_k ao[m,k]*wp[n,k] + bias, K=768.
// Block tile 64x128, 128 threads (4 warps 2x2), warp tile 32x64, BK=32.
// acc 64 regs -> __launch_bounds__(128,4): 4 CTAs/SM, 16 warps/SM; grid
// 768 CTAs on 592 slots (fixes gemm1's 384-on-444 imbalance).
// ---------------------------------------------------------------------------
constexpr int G1_A = 64 * 36 * 4;              // 9216  (one A buffer)
constexpr int G1_B = 128 * 36 * 4;             // 18432 (one B buffer)
constexpr int G1_SMEM_BYTES = 2 * G1_A + 2 * G1_B;   // 55296

__global__ __launch_bounds__(128, 4) void gemm1_tc(
    const float* __restrict__ bias, float* __restrict__ Cout)
{
    extern __shared__ float smem[];

    const int tid  = threadIdx.x;
    const int lane = tid & 31;
    const int warp = tid >> 5;
    const int g  = lane >> 2;
    const int tg = lane & 3;
    const int lb = lane >> 3;
    const int lr = lane & 7;
    const int wm = warp >> 1;      // 0..1 (32-row halves)
    const int wn = warp & 1;       // 0..1 (64-col halves)
    const int row0 = blockIdx.y * 64;
    const int col0 = blockIdx.x * 128;

    const uint32_t abase0 = smem_u32(smem);
    const uint32_t bbase0 = abase0 + 2 * G1_A;

    const uint32_t aoff = (uint32_t)(((wm * 32 + (lb & 1) * 8 + lr) * 36 + (lb >> 1) * 4) * 4);
    const uint32_t boff = (uint32_t)(((wn * 64 + (lb >> 1) * 8 + lr) * 36 + (lb & 1) * 4) * 4);

    float c[2][8][4];
#pragma unroll
    for (int mi = 0; mi < 2; ++mi)
#pragma unroll
        for (int ni = 0; ni < 8; ++ni)
#pragma unroll
            for (int r = 0; r < 4; ++r) c[mi][ni][r] = 0.f;

    auto load_slab = [&](int slab, int buf) {
        const int k0 = slab * 32;
        const uint32_t ab = abase0 + buf * G1_A;
        const uint32_t bb = bbase0 + buf * G1_B;
#pragma unroll
        for (int j = 0; j < 12; ++j) {           // 512 A + 1024 B chunks
            const int id = j * 128 + tid;
            const int isB = (id >= 512);
            const int cid = isB ? (id - 512) : id;
            const int row = cid >> 3;
            const int cc = cid & 7;
            const float* src = (isB ? g_wpc : g_ao)
                + (size_t)((isB ? col0 : row0) + row) * 768 + k0 + cc * 4;
            const uint32_t dst = (isB ? bb : ab) + row * 144 + cc * 16;
            cp16(dst, src);
        }
        cp_commit();
    };

    load_slab(0, 0);

    for (int i = 0; i < 24; ++i) {
        const int cur = i & 1;
        cp_wait_group<0>();
        __syncthreads();

        const uint32_t ab = abase0 + cur * G1_A + aoff;
        const uint32_t bb = bbase0 + cur * G1_B + boff;

        auto do_ks = [&](int ks) {
            const uint32_t kkb = ks * 32;
            uint32_t a[2][4];
#pragma unroll
            for (int mi = 0; mi < 2; ++mi)
                ldsm4(a[mi][0], a[mi][1], a[mi][2], a[mi][3],
                      ab + mi * (16 * 144) + kkb);
            uint32_t b[8][2];
#pragma unroll
            for (int ni2 = 0; ni2 < 4; ++ni2)
                ldsm4(b[2 * ni2][0], b[2 * ni2][1], b[2 * ni2 + 1][0], b[2 * ni2 + 1][1],
                      bb + ni2 * (16 * 144) + kkb);
#pragma unroll
            for (int mi = 0; mi < 2; ++mi)
#pragma unroll
                for (int ni = 0; ni < 8; ++ni)
                    mma8(c[mi][ni], a[mi], b[ni]);
        };

        do_ks(0);
        if (i + 1 < 24) load_slab(i + 1, cur ^ 1);
        do_ks(1); do_ks(2); do_ks(3);
    }

#pragma unroll
    for (int mi = 0; mi < 2; ++mi) {
        const int r = row0 + wm * 32 + mi * 16 + g;
#pragma unroll
        for (int ni = 0; ni < 8; ++ni) {
            const int o = col0 + wn * 64 + ni * 8 + 2 * tg;
            float2 bb = *(const float2*)(bias + o);
            *(float2*)(Cout + (size_t)r * 768 + o) =
                make_float2(c[mi][ni][0] + bb.x, c[mi][ni][1] + bb.y);
            *(float2*)(Cout + (size_t)(r + 8) * 768 + o) =
                make_float2(c[mi][ni][2] + bb.x, c[mi][ni][3] + bb.y);
        }
    }
}

// ---------------------------------------------------------------------------
// Flash attention v3 (unchanged from R13): no-max exp2 softmax, chunked QK,
// PV halves, K dbl-buffered / V single, 3 CTAs/SM.
// ---------------------------------------------------------------------------
constexpr int K_T   = 64 * 68;
constexpr int SM_V  = 2 * K_T;
constexpr int SM_P  = SM_V + K_T;
constexpr int ATT_SMEM_FLOATS = SM_P + 4 * 32 * 36;
constexpr int ATT_SMEM_BYTES = ATT_SMEM_FLOATS * 4;   // 70656

__global__ __launch_bounds__(128, 3) void attn_tc()
{
    extern __shared__ float sm[];
    const int tid  = threadIdx.x;
    const int lane = tid & 31;
    const int warp = tid >> 5;
    const int g  = lane >> 2;
    const int tg = lane & 3;
    const int lb = lane >> 3;
    const int lr = lane & 7;
    const int h2 = blockIdx.y;
    const int b = blockIdx.z;
    const int q0 = blockIdx.x * 128;

    float* Pw = sm + SM_P + warp * (32 * 36);
    const uint32_t smbase = smem_u32(sm);
    const uint32_t pwbase = smbase + (SM_P + warp * (32 * 36)) * 4;

    const size_t head = ((size_t)b * HH + h2) * NN;
    const float* qb = g_q + (head + q0 + warp * 32) * DD;
    const float* kb = g_k + head * DD;
    const float* vb = g_v + head * DD;

    const uint32_t kvoff = (uint32_t)((((lb >> 1) * 8 + lr) * 68 + (lb & 1) * 4) * 4);
    const uint32_t poff  = (uint32_t)((((lb & 1) * 8 + lr) * 36 + (lb >> 1) * 4) * 4);

    auto load_k = [&](int kt, int buf) {
#pragma unroll
        for (int j = 0; j < 8; ++j) {
            const int id = j * 128 + tid;
            const int row = id >> 4, c4 = id & 15;
            cp16(smbase + (uint32_t)(buf * K_T + row * 68) * 4 + c4 * 16,
                 kb + (size_t)(kt * 64 + row) * 64 + c4 * 4);
        }
        cp_commit();
    };
    auto load_v = [&](int kt) {
#pragma unroll
        for (int j = 0; j < 8; ++j) {
            const int id = j * 128 + tid;
            const int row = id >> 4, c4 = id & 15;
            cp16(smbase + (uint32_t)(SM_V + row * 68) * 4 + c4 * 16,
                 vb + (size_t)row * NN + kt * 64 + c4 * 4);
        }
        cp_commit();
    };

    load_k(0, 0);
    load_v(0);

    uint32_t qf[8][8];
#pragma unroll
    for (int ks = 0; ks < 8; ++ks) {
        const int col = ks * 8 + tg;
#pragma unroll
        for (int mi = 0; mi < 2; ++mi) {
            const int row = mi * 16 + g;
            qf[ks][mi * 4 + 0] = __float_as_uint(__ldg(qb + row * 64 + col));
            qf[ks][mi * 4 + 1] = __float_as_uint(__ldg(qb + (row + 8) * 64 + col));
            qf[ks][mi * 4 + 2] = __float_as_uint(__ldg(qb + row * 64 + col + 4));
            qf[ks][mi * 4 + 3] = __float_as_uint(__ldg(qb + (row + 8) * 64 + col + 4));
        }
    }

    float o[2][8][4];
#pragma unroll
    for (int mi = 0; mi < 2; ++mi)
#pragma unroll
        for (int ni = 0; ni < 8; ++ni)
#pragma unroll
            for (int r = 0; r < 4; ++r) o[mi][ni][r] = 0.f;
    float lv[2][2] = { {0.f, 0.f}, {0.f, 0.f} };

    const uint32_t vsb = smbase + (uint32_t)SM_V * 4 + kvoff;

    for (int kt = 0; kt < 16; ++kt) {
        const int cur = kt & 1;
        cp_wait_group<1>();
        __syncthreads();
        if (kt + 1 < 16) load_k(kt + 1, cur ^ 1);

        const uint32_t ksb = smbase + (uint32_t)(cur * K_T) * 4 + kvoff;

#pragma unroll
        for (int h = 0; h < 2; ++h) {
#pragma unroll
            for (int j = 0; j < 2; ++j) {
                const int ni2 = 2 * h + j;
                float s[2][2][4];
#pragma unroll
                for (int mi = 0; mi < 2; ++mi)
#pragma unroll
                    for (int t = 0; t < 2; ++t)
#pragma unroll
                        for (int r = 0; r < 4; ++r) s[mi][t][r] = 0.f;
#pragma unroll
                for (int ks = 0; ks < 8; ++ks) {
                    uint32_t b0, b1, b2, b3;
                    ldsm4(b0, b1, b2, b3, ksb + ni2 * (16 * 68 * 4) + ks * 32);
                    uint32_t bf0[2] = { b0, b1 };
                    uint32_t bf1[2] = { b2, b3 };
                    mma8(s[0][0], &qf[ks][0], bf0);
                    mma8(s[0][1], &qf[ks][0], bf1);
                    mma8(s[1][0], &qf[ks][4], bf0);
                    mma8(s[1][1], &qf[ks][4], bf1);
                }
                const int colb = ni2 * 16 - h * 32 + 2 * tg;
#pragma unroll
                for (int mi = 0; mi < 2; ++mi) {
#pragma unroll
                    for (int t = 0; t < 2; ++t) {
                        const float p0 = exp2f(s[mi][t][0]);
                        const float p1 = exp2f(s[mi][t][1]);
                        const float p2 = exp2f(s[mi][t][2]);
                        const float p3 = exp2f(s[mi][t][3]);
                        lv[mi][0] += p0 + p1;
                        lv[mi][1] += p2 + p3;
                        *(float2*)(Pw + (mi * 16 + g) * 36 + colb + t * 8) =
                            make_float2(f2tf(p0), f2tf(p1));
                        *(float2*)(Pw + (mi * 16 + g + 8) * 36 + colb + t * 8) =
                            make_float2(f2tf(p2), f2tf(p3));
                    }
                }
            }

            if (h == 0) {
                if (kt + 1 < 16) cp_wait_group<1>(); else cp_wait_group<0>();
                __syncthreads();
            } else {
                __syncwarp();
            }

#pragma unroll
            for (int ksl = 0; ksl < 4; ++ksl) {
                uint32_t a[2][4];
#pragma unroll
                for (int mi = 0; mi < 2; ++mi)
                    ldsm4(a[mi][0], a[mi][1], a[mi][2], a[mi][3],
                          pwbase + mi * (16 * 36 * 4) + ksl * 32 + poff);
                uint32_t bfr[8][2];
#pragma unroll
                for (int ni2v = 0; ni2v < 4; ++ni2v)
                    ldsm4(bfr[2 * ni2v][0], bfr[2 * ni2v][1],
                          bfr[2 * ni2v + 1][0], bfr[2 * ni2v + 1][1],
                          vsb + ni2v * (16 * 68 * 4) + (h * 32 + ksl * 8) * 4);
#pragma unroll
                for (int ni = 0; ni < 8; ++ni) {
                    mma8(o[0][ni], a[0], bfr[ni]);
                    mma8(o[1][ni], a[1], bfr[ni]);
                }
            }
            __syncwarp();
        }

        __syncthreads();
        if (kt + 1 < 16) load_v(kt + 1);
    }

#pragma unroll
    for (int mi = 0; mi < 2; ++mi) {
#pragma unroll
        for (int off = 1; off <= 2; off <<= 1) {
            lv[mi][0] += __shfl_xor_sync(0xffffffffu, lv[mi][0], off);
            lv[mi][1] += __shfl_xor_sync(0xffffffffu, lv[mi][1], off);
        }
        const float inv0 = 1.0f / lv[mi][0];
        const float inv1 = 1.0f / lv[mi][1];
        const int rA = q0 + warp * 32 + mi * 16 + g;
        float* aoA = g_ao + ((size_t)b * NN + rA) * CC + h2 * DD;
        float* aoB = g_ao + ((size_t)b * NN + rA + 8) * CC + h2 * DD;
#pragma unroll
        for (int ni = 0; ni < 8; ++ni) {
            const int d = ni * 8 + 2 * tg;
            *(float2*)(aoA + d) =
                make_float2(f2tf(o[mi][ni][0] * inv0), f2tf(o[mi][ni][1] * inv0));
            *(float2*)(aoB + d) =
                make_float2(f2tf(o[mi][ni][2] * inv1), f2tf(o[mi][ni][3] * inv1));
        }
    }
}

// ---------------------------------------------------------------------------
extern "C" void kernel_launch(void* const* d_in, const int* in_sizes, int n_in,
                              void* d_out, int out_size)
{
    const float* x      = (const float*)d_in[0];
    const float* w_qkv  = (const float*)d_in[1];
    const float* w_proj = (const float*)d_in[2];
    const float* b_proj = (const float*)d_in[3];
    float* out = (float*)d_out;

    cudaFuncSetAttribute(gemm0_tc, cudaFuncAttributeMaxDynamicSharedMemorySize, GEMM_SMEM_BYTES);
    cudaFuncSetAttribute(gemm1_tc, cudaFuncAttributeMaxDynamicSharedMemorySize, G1_SMEM_BYTES);
    cudaFuncSetAttribute(attn_tc,  cudaFuncAttributeMaxDynamicSharedMemorySize, ATT_SMEM_BYTES);

    // 0) fused tf32 rounding of x, w_qkv, w_proj
    cvt_all<<<(N4_X + N4_WQ + N4_WP + 255) / 256, 256>>>(
        (const float4*)x, (const float4*)w_qkv, (const float4*)w_proj);

    // 1) QKV projection -> g_q/g_k (row) + g_v (transposed, coalesced)
    gemm0_tc<<<dim3(18, 64), 128, GEMM_SMEM_BYTES>>>();

    // 2) Flash attention per (q-chunk, head, batch)
    attn_tc<<<dim3(8, 12, 8), 128, ATT_SMEM_BYTES>>>();

    // 3) Output projection (64x128 tiles, 4 CTAs/SM) + bias
    gemm1_tc<<<dim3(6, 128), 128, G1_SMEM_BYTES>>>(b_proj, out);
}

// round 16
// speedup vs baseline: 1.8399x; 1.8399x over previous
#include <cuda_runtime.h>
#include <cuda_fp16.h>
#include <cstdint>

// Problem constants
constexpr int BB = 8;
constexpr int NN = 1024;
constexpr int CC = 768;
constexpr int HH = 12;
constexpr int DD = 64;
constexpr float QSCALE = 0.125f;
constexpr float LOG2E  = 1.4426950408889634f;

// Scratch (allocation-free rule: __device__ globals), all fp16
__device__ __align__(16) __half g_qh[BB * HH * NN * DD];   // [B,H,N,D], x0.125*log2e
__device__ __align__(16) __half g_kh[BB * HH * NN * DD];   // [B,H,N,D]
__device__ __align__(16) __half g_vh[BB * HH * NN * DD];   // [B,H,D,N] TRANSPOSED
__device__ __align__(16) __half g_aoh[8192 * 768];         // attention output
__device__ __align__(16) __half g_xh[8192 * 768];
__device__ __align__(16) __half g_wqh[2304 * 768];
__device__ __align__(16) __half g_wph[768 * 768];

// ---------------------------------------------------------------------------
// helpers (portable PTX only — harness compiles at sm_103 (no 'a'))
// ---------------------------------------------------------------------------
__device__ __forceinline__ uint32_t smem_u32(const void* p) {
    uint32_t a;
    asm("{ .reg .u64 t; cvta.to.shared.u64 t, %1; cvt.u32.u64 %0, t; }" : "=r"(a) : "l"(p));
    return a;
}
__device__ __forceinline__ void mma16(float c[4], const uint32_t a[4], const uint32_t b[2]) {
    asm volatile(
        "mma.sync.aligned.m16n8k16.row.col.f32.f16.f16.f32 "
        "{%0,%1,%2,%3},{%4,%5,%6,%7},{%8,%9},{%0,%1,%2,%3};\n"
        : "+f"(c[0]), "+f"(c[1]), "+f"(c[2]), "+f"(c[3])
        : "r"(a[0]), "r"(a[1]), "r"(a[2]), "r"(a[3]), "r"(b[0]), "r"(b[1]));
}
__device__ __forceinline__ void ldsm4(uint32_t& r0, uint32_t& r1, uint32_t& r2,
                                      uint32_t& r3, uint32_t addr) {
    asm volatile("ldmatrix.sync.aligned.m8n8.x4.shared.b16 {%0,%1,%2,%3}, [%4];"
                 : "=r"(r0), "=r"(r1), "=r"(r2), "=r"(r3) : "r"(addr));
}
__device__ __forceinline__ void cp16(uint32_t dst, const void* src) {
    asm volatile("cp.async.cg.shared.global [%0], [%1], 16;" :: "r"(dst), "l"(src));
}
__device__ __forceinline__ void cp_commit() {
    asm volatile("cp.async.commit_group;" ::: "memory");
}
template <int N> __device__ __forceinline__ void cp_wait_group() {
    asm volatile("cp.async.wait_group %0;" :: "n"(N) : "memory");
}
__device__ __forceinline__ uint32_t h2u(__half2 h) {
    return *(uint32_t*)&h;
}

// ---------------------------------------------------------------------------
// fused fp32 -> fp16 conversion of x, w_qkv, w_proj (one launch)
// ---------------------------------------------------------------------------
constexpr int N4_X  = 8192 * 768 / 4;
constexpr int N4_WQ = 2304 * 768 / 4;
constexpr int N4_WP = 768 * 768 / 4;

__global__ __launch_bounds__(256) void cvt_all(
    const float4* __restrict__ x, const float4* __restrict__ wq,
    const float4* __restrict__ wp)
{
    const int i = blockIdx.x * 256 + threadIdx.x;
    const float4* src;
    __half* dst;
    int j = i;
    if (j < N4_X) { src = x; dst = g_xh; }
    else if ((j -= N4_X) < N4_WQ) { src = wq; dst = g_wqh; }
    else if ((j -= N4_WQ) < N4_WP) { src = wp; dst = g_wph; }
    else return;
    float4 v = src[j];
    __half2 h0 = __floats2half2_rn(v.x, v.y);
    __half2 h1 = __floats2half2_rn(v.z, v.w);
    ((__half2*)dst)[2 * j]     = h0;
    ((__half2*)dst)[2 * j + 1] = h1;
}

// ---------------------------------------------------------------------------
// fp16 tensor-core GEMM: C[m,n] = sum_k A[m,k]*W[n,k], K=768.
// Block tile 128x128, 128 threads (4 warps 2x2), warp tile 64x64.
// BK=64 slabs (12 total), cp.async double-buffered, one barrier per slab.
// SMEM row = 64 halves + 8 pad = 144B -> ldmatrix phase rows land on
// distinct bank quads (9r mod 8). m16n8k16 fp16 mma: half the instruction
// count of the tf32 path at identical per-element precision (11-bit mantissa).
// MODE 0: A=g_xh, W=g_wqh -> g_qh/g_kh (row) + g_vh TRANSPOSED [B,H,D,N]
// MODE 1: A=g_aoh, W=g_wph -> d_out (fp32) + bias
// ---------------------------------------------------------------------------
constexpr int TB = 128 * 144;                         // one tile buffer, bytes
constexpr int GEMM_SMEM_BYTES = 4 * TB;               // 73728

template <int MODE>
__global__ __launch_bounds__(128, 3) void gemm_tc(
    const float* __restrict__ bias, float* __restrict__ Cout)
{
    extern __shared__ __half smem[];

    const __half* Ap = (MODE == 0) ? g_xh : g_aoh;
    const __half* W  = (MODE == 0) ? g_wqh : g_wph;

    const int tid  = threadIdx.x;
    const int lane = tid & 31;
    const int warp = tid >> 5;
    const int g  = lane >> 2;
    const int tg = lane & 3;
    const int lb = lane >> 3;
    const int lr = lane & 7;
    const int wm = warp >> 1;
    const int wn = warp & 1;
    const int row0 = blockIdx.y * 128;
    const int col0 = blockIdx.x * 128;

    const uint32_t abase0 = smem_u32(smem);
    const uint32_t bbase0 = abase0 + 2 * TB;

    // A-frag: row=(lb&1)*8+lr, kbyte=(lb>>1)*16 ; B-frag: row=(lb>>1)*8+lr, kbyte=(lb&1)*16
    const uint32_t aoff = (uint32_t)((wm * 64 + (lb & 1) * 8 + lr) * 144 + (lb >> 1) * 16);
    const uint32_t boff = (uint32_t)((wn * 64 + (lb >> 1) * 8 + lr) * 144 + (lb & 1) * 16);

    float c[4][8][4];
#pragma unroll
    for (int mi = 0; mi < 4; ++mi)
#pragma unroll
        for (int ni = 0; ni < 8; ++ni)
#pragma unroll
            for (int r = 0; r < 4; ++r) c[mi][ni][r] = 0.f;

    auto load_slab = [&](int slab, int buf) {
        const int k0 = slab * 64;
        const uint32_t ab = abase0 + buf * TB;
        const uint32_t bb = bbase0 + buf * TB;
#pragma unroll
        for (int j = 0; j < 16; ++j) {
            const int id = j * 128 + tid;
            const int isB = id >> 10;
            const int cid = id & 1023;
            const int row = cid >> 3;
            const int cc = cid & 7;
            const __half* src = (isB ? W : Ap)
                + (size_t)((isB ? col0 : row0) + row) * 768 + k0 + cc * 8;
            const uint32_t dst = (isB ? bb : ab) + row * 144 + cc * 16;
            cp16(dst, src);
        }
        cp_commit();
    };

    load_slab(0, 0);

    for (int i = 0; i < 12; ++i) {
        const int cur = i & 1;
        cp_wait_group<0>();
        __syncthreads();

        const uint32_t ab = abase0 + cur * TB + aoff;
        const uint32_t bb = bbase0 + cur * TB + boff;

        auto do_ks = [&](int ks) {
            const uint32_t kkb = ks * 32;              // 16 halves per k-step
            uint32_t a[4][4];
#pragma unroll
            for (int mi = 0; mi < 4; ++mi)
                ldsm4(a[mi][0], a[mi][1], a[mi][2], a[mi][3],
                      ab + mi * (16 * 144) + kkb);
            uint32_t b[8][2];
#pragma unroll
            for (int ni2 = 0; ni2 < 4; ++ni2)
                ldsm4(b[2 * ni2][0], b[2 * ni2][1], b[2 * ni2 + 1][0], b[2 * ni2 + 1][1],
                      bb + ni2 * (16 * 144) + kkb);
#pragma unroll
            for (int mi = 0; mi < 4; ++mi)
#pragma unroll
                for (int ni = 0; ni < 8; ++ni)
                    mma16(c[mi][ni], a[mi], b[ni]);
        };

        do_ks(0);
        if (i + 1 < 12) load_slab(i + 1, cur ^ 1);
        do_ks(1); do_ks(2); do_ks(3);
    }

    if (MODE == 0) {
        const int s = col0 / 768;                       // 0=q,1=k,2=v
        const int colr = col0 - s * 768;
        if (s == 2) {
            // V transposed scatter (half stores; CTA fully covers each
            // 256B [d]-row segment -> L2 coalesces writes)
#pragma unroll
            for (int mi = 0; mi < 4; ++mi) {
                const int r = row0 + wm * 64 + mi * 16 + g;
                const int b = r >> 10, n0 = r & 1023, n1 = (r + 8) & 1023;
#pragma unroll
                for (int ni = 0; ni < 8; ++ni) {
                    const int o = colr + wn * 64 + ni * 8 + 2 * tg;
                    const int h = o >> 6, d = o & 63;
                    __half* dst = g_vh + (((size_t)b * HH + h) * DD + d) * NN;
                    dst[n0]      = __float2half_rn(c[mi][ni][0]);
                    dst[NN + n0] = __float2half_rn(c[mi][ni][1]);
                    dst[n1]      = __float2half_rn(c[mi][ni][2]);
                    dst[NN + n1] = __float2half_rn(c[mi][ni][3]);
                }
            }
        } else {
            __half* dstb = (s == 0) ? g_qh : g_kh;
            const float mul = (s == 0) ? QSCALE * LOG2E : 1.0f;
#pragma unroll
            for (int mi = 0; mi < 4; ++mi) {
                const int r = row0 + wm * 64 + mi * 16 + g;
                const int b = r >> 10, n0 = r & 1023, n1 = (r + 8) & 1023;
#pragma unroll
                for (int ni = 0; ni < 8; ++ni) {
                    const int o = colr + wn * 64 + ni * 8 + 2 * tg;
                    const int h = o >> 6, d = o & 63;
                    const size_t base = ((size_t)b * HH + h) * NN;
                    *(__half2*)(dstb + (base + n0) * DD + d) =
                        __floats2half2_rn(c[mi][ni][0] * mul, c[mi][ni][1] * mul);
                    *(__half2*)(dstb + (base + n1) * DD + d) =
                        __floats2half2_rn(c[mi][ni][2] * mul, c[mi][ni][3] * mul);
                }
            }
        }
    } else {
#pragma unroll
        for (int mi = 0; mi < 4; ++mi) {
            const int r = row0 + wm * 64 + mi * 16 + g;
#pragma unroll
            for (int ni = 0; ni < 8; ++ni) {
                const int o = col0 + wn * 64 + ni * 8 + 2 * tg;
                float2 bb = *(const float2*)(bias + o);
                *(float2*)(Cout + (size_t)r * 768 + o) =
                    make_float2(c[mi][ni][0] + bb.x, c[mi][ni][1] + bb.y);
                *(float2*)(Cout + (size_t)(r + 8) * 768 + o) =
                    make_float2(c[mi][ni][2] + bb.x, c[mi][ni][3] + bb.y);
            }
        }
    }
}

// ---------------------------------------------------------------------------
// Flash attention, fp16 mma (m16n8k16), no-max exp2 softmax, chunked QK,
// PV in two 32-key halves. K dbl-buffered, V single-buffered.
// K/V smem rows: 64 halves + 8 pad = 144B; P rows: 32 halves + 8 pad = 80B.
// Block = 128 q-rows of one (b,h); 128 threads, 4 warps x 32 q-rows.
// ---------------------------------------------------------------------------
constexpr int K_TB   = 64 * 144;             // one K or V tile, bytes (9216)
constexpr int SM_VB  = 2 * K_TB;             // V tile offset (bytes)
constexpr int SM_PB  = SM_VB + K_TB;         // P buffers offset (bytes)
constexpr int P_WB   = 32 * 80;              // per-warp P buffer (2560)
constexpr int ATT_SMEM_BYTES = SM_PB + 4 * P_WB;   // 37888

__global__ __launch_bounds__(128, 3) void attn_tc()
{
    extern __shared__ __half sm[];
    const int tid  = threadIdx.x;
    const int lane = tid & 31;
    const int warp = tid >> 5;
    const int g  = lane >> 2;
    const int tg = lane & 3;
    const int lb = lane >> 3;
    const int lr = lane & 7;
    const int h2 = blockIdx.y;
    const int b = blockIdx.z;
    const int q0 = blockIdx.x * 128;

    const uint32_t smbase = smem_u32(sm);
    const uint32_t pwbase = smbase + SM_PB + warp * P_WB;
    __half* Pw = sm + (SM_PB + warp * P_WB) / 2;

    const size_t head = ((size_t)b * HH + h2) * NN;
    const __half* qb = g_qh + (head + q0 + warp * 32) * DD;
    const __half* kb = g_kh + head * DD;               // [key][d]
    const __half* vb = g_vh + head * DD;               // [d][key]

    const uint32_t kvoff = (uint32_t)(((lb >> 1) * 8 + lr) * 144 + (lb & 1) * 16);  // B-type
    const uint32_t poff  = (uint32_t)(((lb & 1) * 8 + lr) * 80 + (lb >> 1) * 16);   // A-type

    auto load_k = [&](int kt, int buf) {
#pragma unroll
        for (int j = 0; j < 4; ++j) {
            const int id = j * 128 + tid;
            const int row = id >> 3, c8 = id & 7;
            cp16(smbase + (uint32_t)(buf * K_TB + row * 144) + c8 * 16,
                 kb + (size_t)(kt * 64 + row) * 64 + c8 * 8);
        }
        cp_commit();
    };
    auto load_v = [&](int kt) {
#pragma unroll
        for (int j = 0; j < 4; ++j) {
            const int id = j * 128 + tid;
            const int row = id >> 3, c8 = id & 7;   // row = d
            cp16(smbase + (uint32_t)(SM_VB + row * 144) + c8 * 16,
                 vb + (size_t)row * NN + kt * 64 + c8 * 8);
        }
        cp_commit();
    };

    load_k(0, 0);
    load_v(0);

    // ---- Q fragments: gmem half2 loads (one-time) ----
    uint32_t qf[4][8];                   // [ks d-step][mi*4+r]
#pragma unroll
    for (int ks = 0; ks < 4; ++ks) {
#pragma unroll
        for (int mi = 0; mi < 2; ++mi) {
            const int row = mi * 16 + g;
            qf[ks][mi * 4 + 0] = h2u(__ldg((const __half2*)(qb + row * 64 + ks * 16 + 2 * tg)));
            qf[ks][mi * 4 + 1] = h2u(__ldg((const __half2*)(qb + (row + 8) * 64 + ks * 16 + 2 * tg)));
            qf[ks][mi * 4 + 2] = h2u(__ldg((const __half2*)(qb + row * 64 + ks * 16 + 8 + 2 * tg)));
            qf[ks][mi * 4 + 3] = h2u(__ldg((const __half2*)(qb + (row + 8) * 64 + ks * 16 + 8 + 2 * tg)));
        }
    }

    float o[2][8][4];
#pragma unroll
    for (int mi = 0; mi < 2; ++mi)
#pragma unroll
        for (int ni = 0; ni < 8; ++ni)
#pragma unroll
            for (int r = 0; r < 4; ++r) o[mi][ni][r] = 0.f;
    float lv[2][2] = { {0.f, 0.f}, {0.f, 0.f} };

    const uint32_t vsb = smbase + SM_VB + kvoff;

    for (int kt = 0; kt < 16; ++kt) {
        const int cur = kt & 1;
        cp_wait_group<1>();
        __syncthreads();
        if (kt + 1 < 16) load_k(kt + 1, cur ^ 1);

        const uint32_t ksb = smbase + cur * K_TB + kvoff;

#pragma unroll
        for (int h = 0; h < 2; ++h) {
            // ---- QK + exp for this half's two 16-key chunks ----
#pragma unroll
            for (int j = 0; j < 2; ++j) {
                const int ni2 = 2 * h + j;
                float s[2][2][4];
#pragma unroll
                for (int mi = 0; mi < 2; ++mi)
#pragma unroll
                    for (int t = 0; t < 2; ++t)
#pragma unroll
                        for (int r = 0; r < 4; ++r) s[mi][t][r] = 0.f;
#pragma unroll
                for (int ks = 0; ks < 4; ++ks) {       // d k-steps (16 each)
                    uint32_t b0, b1, b2, b3;
                    ldsm4(b0, b1, b2, b3, ksb + ni2 * (16 * 144) + ks * 32);
                    uint32_t bf0[2] = { b0, b1 };
                    uint32_t bf1[2] = { b2, b3 };
                    mma16(s[0][0], &qf[ks][0], bf0);
                    mma16(s[0][1], &qf[ks][0], bf1);
                    mma16(s[1][0], &qf[ks][4], bf0);
                    mma16(s[1][1], &qf[ks][4], bf1);
                }
                const int colb = ni2 * 16 - h * 32 + 2 * tg;   // half index in 32-key row
#pragma unroll
                for (int mi = 0; mi < 2; ++mi) {
#pragma unroll
                    for (int t = 0; t < 2; ++t) {
                        const float p0 = exp2f(s[mi][t][0]);
                        const float p1 = exp2f(s[mi][t][1]);
                        const float p2 = exp2f(s[mi][t][2]);
                        const float p3 = exp2f(s[mi][t][3]);
                        lv[mi][0] += p0 + p1;
                        lv[mi][1] += p2 + p3;
                        *(__half2*)(Pw + (mi * 16 + g) * 40 + colb + t * 8) =
                            __floats2half2_rn(p0, p1);
                        *(__half2*)(Pw + (mi * 16 + g + 8) * 40 + colb + t * 8) =
                            __floats2half2_rn(p2, p3);
                    }
                }
            }

            if (h == 0) {
                if (kt + 1 < 16) cp_wait_group<1>(); else cp_wait_group<0>();
                __syncthreads();               // V visible
            } else {
                __syncwarp();                  // P stores -> PV reads
            }

            // ---- PV for this half (keys 32h..32h+31), 2 k16-steps ----
#pragma unroll
            for (int ksl = 0; ksl < 2; ++ksl) {
                uint32_t a[2][4];
#pragma unroll
                for (int mi = 0; mi < 2; ++mi)
                    ldsm4(a[mi][0], a[mi][1], a[mi][2], a[mi][3],
                          pwbase + mi * (16 * 80) + ksl * 32 + poff);
                uint32_t bfr[8][2];
#pragma unroll
                for (int ni2v = 0; ni2v < 4; ++ni2v)
                    ldsm4(bfr[2 * ni2v][0], bfr[2 * ni2v][1],
                          bfr[2 * ni2v + 1][0], bfr[2 * ni2v + 1][1],
                          vsb + ni2v * (16 * 144) + (h * 32 + ksl * 16) * 2);
#pragma unroll
                for (int ni = 0; ni < 8; ++ni) {
                    mma16(o[0][ni], a[0], bfr[ni]);
                    mma16(o[1][ni], a[1], bfr[ni]);
                }
            }
            __syncwarp();
        }

        __syncthreads();                       // all warps done reading V(kt)
        if (kt + 1 < 16) load_v(kt + 1);
    }

    // ---- final l reduction + epilogue: fp16 g_aoh ----
#pragma unroll
    for (int mi = 0; mi < 2; ++mi) {
#pragma unroll
        for (int off = 1; off <= 2; off <<= 1) {
            lv[mi][0] += __shfl_xor_sync(0xffffffffu, lv[mi][0], off);
            lv[mi][1] += __shfl_xor_sync(0xffffffffu, lv[mi][1], off);
        }
        const float inv0 = 1.0f / lv[mi][0];
        const float inv1 = 1.0f / lv[mi][1];
        const int rA = q0 + warp * 32 + mi * 16 + g;
        __half* aoA = g_aoh + ((size_t)b * NN + rA) * CC + h2 * DD;
        __half* aoB = g_aoh + ((size_t)b * NN + rA + 8) * CC + h2 * DD;
#pragma unroll
        for (int ni = 0; ni < 8; ++ni) {
            const int d = ni * 8 + 2 * tg;
            *(__half2*)(aoA + d) = __floats2half2_rn(o[mi][ni][0] * inv0, o[mi][ni][1] * inv0);
            *(__half2*)(aoB + d) = __floats2half2_rn(o[mi][ni][2] * inv1, o[mi][ni][3] * inv1);
        }
    }
}

// ---------------------------------------------------------------------------
extern "C" void kernel_launch(void* const* d_in, const int* in_sizes, int n_in,
                              void* d_out, int out_size)
{
    const float* x      = (const float*)d_in[0];
    const float* w_qkv  = (const float*)d_in[1];
    const float* w_proj = (const float*)d_in[2];
    const float* b_proj = (const float*)d_in[3];
    float* out = (float*)d_out;

    cudaFuncSetAttribute(gemm_tc<0>, cudaFuncAttributeMaxDynamicSharedMemorySize, GEMM_SMEM_BYTES);
    cudaFuncSetAttribute(gemm_tc<1>, cudaFuncAttributeMaxDynamicSharedMemorySize, GEMM_SMEM_BYTES);
    cudaFuncSetAttribute(attn_tc,   cudaFuncAttributeMaxDynamicSharedMemorySize, ATT_SMEM_BYTES);

    // 0) fused fp16 conversion of x, w_qkv, w_proj
    cvt_all<<<(N4_X + N4_WQ + N4_WP + 255) / 256, 256>>>(
        (const float4*)x, (const float4*)w_qkv, (const float4*)w_proj);

    // 1) QKV projection -> g_qh/g_kh (row) + g_vh (transposed)
    gemm_tc<0><<<dim3(18, 64), 128, GEMM_SMEM_BYTES>>>(nullptr, nullptr);

    // 2) Flash attention per (q-chunk, head, batch)
    attn_tc<<<dim3(8, 12, 8), 128, ATT_SMEM_BYTES>>>();

    // 3) Output projection + bias -> fp32 out
    gemm_tc<1><<<dim3(6, 64), 128, GEMM_SMEM_BYTES>>>(b_proj, out);
}

// round 17
// speedup vs baseline: 1.8726x; 1.0178x over previous
#include <cuda_runtime.h>
#include <cuda_fp16.h>
#include <cstdint>

// Problem constants
constexpr int BB = 8;
constexpr int NN = 1024;
constexpr int CC = 768;
constexpr int HH = 12;
constexpr int DD = 64;
constexpr float QSCALE = 0.125f;
constexpr float LOG2E  = 1.4426950408889634f;

// Scratch (allocation-free rule: __device__ globals), all fp16
__device__ __align__(16) __half g_qh[BB * HH * NN * DD];   // [B,H,N,D], x0.125*log2e
__device__ __align__(16) __half g_kh[BB * HH * NN * DD];   // [B,H,N,D]
__device__ __align__(16) __half g_vh[BB * HH * NN * DD];   // [B,H,D,N] TRANSPOSED
__device__ __align__(16) __half g_aoh[8192 * 768];         // attention output
__device__ __align__(16) __half g_xh[8192 * 768];
__device__ __align__(16) __half g_wqh[2304 * 768];
__device__ __align__(16) __half g_wph[768 * 768];

// ---------------------------------------------------------------------------
// helpers (portable PTX only — harness compiles at sm_103 (no 'a'))
// ---------------------------------------------------------------------------
__device__ __forceinline__ uint32_t smem_u32(const void* p) {
    uint32_t a;
    asm("{ .reg .u64 t; cvta.to.shared.u64 t, %1; cvt.u32.u64 %0, t; }" : "=r"(a) : "l"(p));
    return a;
}
__device__ __forceinline__ void mma16(float c[4], const uint32_t a[4], const uint32_t b[2]) {
    asm volatile(
        "mma.sync.aligned.m16n8k16.row.col.f32.f16.f16.f32 "
        "{%0,%1,%2,%3},{%4,%5,%6,%7},{%8,%9},{%0,%1,%2,%3};\n"
        : "+f"(c[0]), "+f"(c[1]), "+f"(c[2]), "+f"(c[3])
        : "r"(a[0]), "r"(a[1]), "r"(a[2]), "r"(a[3]), "r"(b[0]), "r"(b[1]));
}
__device__ __forceinline__ void ldsm4(uint32_t& r0, uint32_t& r1, uint32_t& r2,
                                      uint32_t& r3, uint32_t addr) {
    asm volatile("ldmatrix.sync.aligned.m8n8.x4.shared.b16 {%0,%1,%2,%3}, [%4];"
                 : "=r"(r0), "=r"(r1), "=r"(r2), "=r"(r3) : "r"(addr));
}
__device__ __forceinline__ void cp16(uint32_t dst, const void* src) {
    asm volatile("cp.async.cg.shared.global [%0], [%1], 16;" :: "r"(dst), "l"(src));
}
__device__ __forceinline__ void cp_commit() {
    asm volatile("cp.async.commit_group;" ::: "memory");
}
template <int N> __device__ __forceinline__ void cp_wait_group() {
    asm volatile("cp.async.wait_group %0;" :: "n"(N) : "memory");
}
__device__ __forceinline__ uint32_t h2u(__half2 h) {
    return *(uint32_t*)&h;
}

// ---------------------------------------------------------------------------
// fused fp32 -> fp16 conversion of x, w_qkv, w_proj (one launch)
// ---------------------------------------------------------------------------
constexpr int N4_X  = 8192 * 768 / 4;
constexpr int N4_WQ = 2304 * 768 / 4;
constexpr int N4_WP = 768 * 768 / 4;

__global__ __launch_bounds__(256) void cvt_all(
    const float4* __restrict__ x, const float4* __restrict__ wq,
    const float4* __restrict__ wp)
{
    const int i = blockIdx.x * 256 + threadIdx.x;
    const float4* src;
    __half* dst;
    int j = i;
    if (j < N4_X) { src = x; dst = g_xh; }
    else if ((j -= N4_X) < N4_WQ) { src = wq; dst = g_wqh; }
    else if ((j -= N4_WQ) < N4_WP) { src = wp; dst = g_wph; }
    else return;
    float4 v = src[j];
    ((__half2*)dst)[2 * j]     = __floats2half2_rn(v.x, v.y);
    ((__half2*)dst)[2 * j + 1] = __floats2half2_rn(v.z, v.w);
}

// ---------------------------------------------------------------------------
// QKV GEMM (gemm0), fp16 m16n8k16, 256 threads / 8 warps (2x4),
// warp tile 64x32 (acc 64 regs) -> __launch_bounds__(256,2): 16 warps/SM
// (fp16 halved the crossbar ratio, so the R8 occupancy lever is live again).
// Block tile 128x128, BK=64 slabs (12), cp.async double-buffered.
// -> g_qh/g_kh (row-major) + g_vh TRANSPOSED [B,H,D,N]
// ---------------------------------------------------------------------------
constexpr int TB = 128 * 144;                         // one tile buffer, bytes
constexpr int GEMM_SMEM_BYTES = 4 * TB;               // 73728

__global__ __launch_bounds__(256, 2) void gemm0_tc()
{
    extern __shared__ __half smem[];

    const int tid  = threadIdx.x;
    const int lane = tid & 31;
    const int warp = tid >> 5;
    const int g  = lane >> 2;
    const int tg = lane & 3;
    const int lb = lane >> 3;
    const int lr = lane & 7;
    const int wm = warp >> 2;      // 0..1 (64-row halves)
    const int wn = warp & 3;       // 0..3 (32-col quarters)
    const int row0 = blockIdx.y * 128;
    const int col0 = blockIdx.x * 128;

    const uint32_t abase0 = smem_u32(smem);
    const uint32_t bbase0 = abase0 + 2 * TB;

    const uint32_t aoff = (uint32_t)((wm * 64 + (lb & 1) * 8 + lr) * 144 + (lb >> 1) * 16);
    const uint32_t boff = (uint32_t)((wn * 32 + (lb >> 1) * 8 + lr) * 144 + (lb & 1) * 16);

    float c[4][4][4];
#pragma unroll
    for (int mi = 0; mi < 4; ++mi)
#pragma unroll
        for (int ni = 0; ni < 4; ++ni)
#pragma unroll
            for (int r = 0; r < 4; ++r) c[mi][ni][r] = 0.f;

    auto load_slab = [&](int slab, int buf) {
        const int k0 = slab * 64;
        const uint32_t ab = abase0 + buf * TB;
        const uint32_t bb = bbase0 + buf * TB;
#pragma unroll
        for (int j = 0; j < 8; ++j) {
            const int id = j * 256 + tid;
            const int isB = id >> 10;
            const int cid = id & 1023;
            const int row = cid >> 3;
            const int cc = cid & 7;
            const __half* src = (isB ? g_wqh : g_xh)
                + (size_t)((isB ? col0 : row0) + row) * 768 + k0 + cc * 8;
            const uint32_t dst = (isB ? bb : ab) + row * 144 + cc * 16;
            cp16(dst, src);
        }
        cp_commit();
    };

    load_slab(0, 0);

    for (int i = 0; i < 12; ++i) {
        const int cur = i & 1;
        cp_wait_group<0>();
        __syncthreads();

        const uint32_t ab = abase0 + cur * TB + aoff;
        const uint32_t bb = bbase0 + cur * TB + boff;

        auto do_ks = [&](int ks) {
            const uint32_t kkb = ks * 32;              // 16 halves per k-step
            uint32_t a[4][4];
#pragma unroll
            for (int mi = 0; mi < 4; ++mi)
                ldsm4(a[mi][0], a[mi][1], a[mi][2], a[mi][3],
                      ab + mi * (16 * 144) + kkb);
            uint32_t b[4][2];
#pragma unroll
            for (int ni2 = 0; ni2 < 2; ++ni2)
                ldsm4(b[2 * ni2][0], b[2 * ni2][1], b[2 * ni2 + 1][0], b[2 * ni2 + 1][1],
                      bb + ni2 * (16 * 144) + kkb);
#pragma unroll
            for (int mi = 0; mi < 4; ++mi)
#pragma unroll
                for (int ni = 0; ni < 4; ++ni)
                    mma16(c[mi][ni], a[mi], b[ni]);
        };

        do_ks(0);
        if (i + 1 < 12) load_slab(i + 1, cur ^ 1);
        do_ks(1); do_ks(2); do_ks(3);
    }

    const int s = col0 / 768;                       // 0=q,1=k,2=v
    const int colr = col0 - s * 768;
    if (s == 2) {
#pragma unroll
        for (int mi = 0; mi < 4; ++mi) {
            const int r = row0 + wm * 64 + mi * 16 + g;
            const int b = r >> 10, n0 = r & 1023, n1 = (r + 8) & 1023;
#pragma unroll
            for (int ni = 0; ni < 4; ++ni) {
                const int o = colr + wn * 32 + ni * 8 + 2 * tg;
                const int h = o >> 6, d = o & 63;
                __half* dst = g_vh + (((size_t)b * HH + h) * DD + d) * NN;
                dst[n0]      = __float2half_rn(c[mi][ni][0]);
                dst[NN + n0] = __float2half_rn(c[mi][ni][1]);
                dst[n1]      = __float2half_rn(c[mi][ni][2]);
                dst[NN + n1] = __float2half_rn(c[mi][ni][3]);
            }
        }
    } else {
        __half* dstb = (s == 0) ? g_qh : g_kh;
        const float mul = (s == 0) ? QSCALE * LOG2E : 1.0f;
#pragma unroll
        for (int mi = 0; mi < 4; ++mi) {
            const int r = row0 + wm * 64 + mi * 16 + g;
            const int b = r >> 10, n0 = r & 1023, n1 = (r + 8) & 1023;
#pragma unroll
            for (int ni = 0; ni < 4; ++ni) {
                const int o = colr + wn * 32 + ni * 8 + 2 * tg;
                const int h = o >> 6, d = o & 63;
                const size_t base = ((size_t)b * HH + h) * NN;
                *(__half2*)(dstb + (base + n0) * DD + d) =
                    __floats2half2_rn(c[mi][ni][0] * mul, c[mi][ni][1] * mul);
                *(__half2*)(dstb + (base + n1) * DD + d) =
                    __floats2half2_rn(c[mi][ni][2] * mul, c[mi][ni][3] * mul);
            }
        }
    }
}

// ---------------------------------------------------------------------------
// Output projection (gemm1): unchanged proven R16 config.
// 128 threads (4 warps 2x2), warp tile 64x64, block 128x128, BK=64.
// ---------------------------------------------------------------------------
__global__ __launch_bounds__(128, 3) void gemm1_tc(
    const float* __restrict__ bias, float* __restrict__ Cout)
{
    extern __shared__ __half smem[];

    const int tid  = threadIdx.x;
    const int lane = tid & 31;
    const int warp = tid >> 5;
    const int g  = lane >> 2;
    const int tg = lane & 3;
    const int lb = lane >> 3;
    const int lr = lane & 7;
    const int wm = warp >> 1;
    const int wn = warp & 1;
    const int row0 = blockIdx.y * 128;
    const int col0 = blockIdx.x * 128;

    const uint32_t abase0 = smem_u32(smem);
    const uint32_t bbase0 = abase0 + 2 * TB;

    const uint32_t aoff = (uint32_t)((wm * 64 + (lb & 1) * 8 + lr) * 144 + (lb >> 1) * 16);
    const uint32_t boff = (uint32_t)((wn * 64 + (lb >> 1) * 8 + lr) * 144 + (lb & 1) * 16);

    float c[4][8][4];
#pragma unroll
    for (int mi = 0; mi < 4; ++mi)
#pragma unroll
        for (int ni = 0; ni < 8; ++ni)
#pragma unroll
            for (int r = 0; r < 4; ++r) c[mi][ni][r] = 0.f;

    auto load_slab = [&](int slab, int buf) {
        const int k0 = slab * 64;
        const uint32_t ab = abase0 + buf * TB;
        const uint32_t bb = bbase0 + buf * TB;
#pragma unroll
        for (int j = 0; j < 16; ++j) {
            const int id = j * 128 + tid;
            const int isB = id >> 10;
            const int cid = id & 1023;
            const int row = cid >> 3;
            const int cc = cid & 7;
            const __half* src = (isB ? g_wph : g_aoh)
                + (size_t)((isB ? col0 : row0) + row) * 768 + k0 + cc * 8;
            const uint32_t dst = (isB ? bb : ab) + row * 144 + cc * 16;
            cp16(dst, src);
        }
        cp_commit();
    };

    load_slab(0, 0);

    for (int i = 0; i < 12; ++i) {
        const int cur = i & 1;
        cp_wait_group<0>();
        __syncthreads();

        const uint32_t ab = abase0 + cur * TB + aoff;
        const uint32_t bb = bbase0 + cur * TB + boff;

        auto do_ks = [&](int ks) {
            const uint32_t kkb = ks * 32;
            uint32_t a[4][4];
#pragma unroll
            for (int mi = 0; mi < 4; ++mi)
                ldsm4(a[mi][0], a[mi][1], a[mi][2], a[mi][3],
                      ab + mi * (16 * 144) + kkb);
            uint32_t b[8][2];
#pragma unroll
            for (int ni2 = 0; ni2 < 4; ++ni2)
                ldsm4(b[2 * ni2][0], b[2 * ni2][1], b[2 * ni2 + 1][0], b[2 * ni2 + 1][1],
                      bb + ni2 * (16 * 144) + kkb);
#pragma unroll
            for (int mi = 0; mi < 4; ++mi)
#pragma unroll
                for (int ni = 0; ni < 8; ++ni)
                    mma16(c[mi][ni], a[mi], b[ni]);
        };

        do_ks(0);
        if (i + 1 < 12) load_slab(i + 1, cur ^ 1);
        do_ks(1); do_ks(2); do_ks(3);
    }

#pragma unroll
    for (int mi = 0; mi < 4; ++mi) {
        const int r = row0 + wm * 64 + mi * 16 + g;
#pragma unroll
        for (int ni = 0; ni < 8; ++ni) {
            const int o = col0 + wn * 64 + ni * 8 + 2 * tg;
            float2 bb = *(const float2*)(bias + o);
            *(float2*)(Cout + (size_t)r * 768 + o) =
                make_float2(c[mi][ni][0] + bb.x, c[mi][ni][1] + bb.y);
            *(float2*)(Cout + (size_t)(r + 8) * 768 + o) =
                make_float2(c[mi][ni][2] + bb.x, c[mi][ni][3] + bb.y);
        }
    }
}

// ---------------------------------------------------------------------------
// Flash attention v4: K AND V double-buffered, loaded in ONE commit group
// per tile -> gemm-style pipeline with ONE __syncthreads per tile (no
// mid-tile V wait). fp16 m16n8k16, no-max exp2 softmax, chunked QK, PV in
// two 32-key halves. smem 47104B -> 3 CTAs/SM.
// Layout: K0 | K1 | V0 | V1 | P(4 warps)
// ---------------------------------------------------------------------------
constexpr int K_TB   = 64 * 144;             // one K or V tile, bytes (9216)
constexpr int SM_PB  = 4 * K_TB;             // P buffers offset (bytes)
constexpr int P_WB   = 32 * 80;              // per-warp P buffer (2560)
constexpr int ATT_SMEM_BYTES = SM_PB + 4 * P_WB;   // 47104

__global__ __launch_bounds__(128, 3) void attn_tc()
{
    extern __shared__ __half sm[];
    const int tid  = threadIdx.x;
    const int lane = tid & 31;
    const int warp = tid >> 5;
    const int g  = lane >> 2;
    const int tg = lane & 3;
    const int lb = lane >> 3;
    const int lr = lane & 7;
    const int h2 = blockIdx.y;
    const int b = blockIdx.z;
    const int q0 = blockIdx.x * 128;

    const uint32_t smbase = smem_u32(sm);
    const uint32_t pwbase = smbase + SM_PB + warp * P_WB;
    __half* Pw = sm + (SM_PB + warp * P_WB) / 2;

    const size_t head = ((size_t)b * HH + h2) * NN;
    const __half* qb = g_qh + (head + q0 + warp * 32) * DD;
    const __half* kb = g_kh + head * DD;               // [key][d]
    const __half* vb = g_vh + head * DD;               // [d][key]

    const uint32_t kvoff = (uint32_t)(((lb >> 1) * 8 + lr) * 144 + (lb & 1) * 16);  // B-type
    const uint32_t poff  = (uint32_t)(((lb & 1) * 8 + lr) * 80 + (lb >> 1) * 16);   // A-type

    // one commit group: K tile + V tile for (kt, buf)
    auto load_tile = [&](int kt, int buf) {
#pragma unroll
        for (int j = 0; j < 8; ++j) {
            const int id = j * 128 + tid;
            const int isV = id >> 9;              // 512 K + 512 V chunks
            const int cid = id & 511;
            const int row = cid >> 3, c8 = cid & 7;
            const __half* src = isV
                ? vb + (size_t)row * NN + kt * 64 + c8 * 8
                : kb + (size_t)(kt * 64 + row) * 64 + c8 * 8;
            const uint32_t dst = smbase
                + (uint32_t)(((isV ? 2 : 0) + buf) * K_TB + row * 144) + c8 * 16;
            cp16(dst, src);
        }
        cp_commit();
    };

    load_tile(0, 0);

    // ---- Q fragments: gmem half2 loads (one-time) ----
    uint32_t qf[4][8];
#pragma unroll
    for (int ks = 0; ks < 4; ++ks) {
#pragma unroll
        for (int mi = 0; mi < 2; ++mi) {
            const int row = mi * 16 + g;
            qf[ks][mi * 4 + 0] = h2u(__ldg((const __half2*)(qb + row * 64 + ks * 16 + 2 * tg)));
            qf[ks][mi * 4 + 1] = h2u(__ldg((const __half2*)(qb + (row + 8) * 64 + ks * 16 + 2 * tg)));
            qf[ks][mi * 4 + 2] = h2u(__ldg((const __half2*)(qb + row * 64 + ks * 16 + 8 + 2 * tg)));
            qf[ks][mi * 4 + 3] = h2u(__ldg((const __half2*)(qb + (row + 8) * 64 + ks * 16 + 8 + 2 * tg)));
        }
    }

    float o[2][8][4];
#pragma unroll
    for (int mi = 0; mi < 2; ++mi)
#pragma unroll
        for (int ni = 0; ni < 8; ++ni)
#pragma unroll
            for (int r = 0; r < 4; ++r) o[mi][ni][r] = 0.f;
    float lv[2][2] = { {0.f, 0.f}, {0.f, 0.f} };

    for (int kt = 0; kt < 16; ++kt) {
        const int cur = kt & 1;
        cp_wait_group<0>();                    // K+V of tile kt landed
        __syncthreads();                       // visible; buffers cur^1 free
        if (kt + 1 < 16) load_tile(kt + 1, cur ^ 1);

        const uint32_t ksb = smbase + cur * K_TB + kvoff;
        const uint32_t vsb = smbase + (2 + cur) * K_TB + kvoff;

#pragma unroll
        for (int h = 0; h < 2; ++h) {
            // ---- QK + exp for this half's two 16-key chunks ----
#pragma unroll
            for (int j = 0; j < 2; ++j) {
                const int ni2 = 2 * h + j;
                float s[2][2][4];
#pragma unroll
                for (int mi = 0; mi < 2; ++mi)
#pragma unroll
                    for (int t = 0; t < 2; ++t)
#pragma unroll
                        for (int r = 0; r < 4; ++r) s[mi][t][r] = 0.f;
#pragma unroll
                for (int ks = 0; ks < 4; ++ks) {
                    uint32_t b0, b1, b2, b3;
                    ldsm4(b0, b1, b2, b3, ksb + ni2 * (16 * 144) + ks * 32);
                    uint32_t bf0[2] = { b0, b1 };
                    uint32_t bf1[2] = { b2, b3 };
                    mma16(s[0][0], &qf[ks][0], bf0);
                    mma16(s[0][1], &qf[ks][0], bf1);
                    mma16(s[1][0], &qf[ks][4], bf0);
                    mma16(s[1][1], &qf[ks][4], bf1);
                }
                const int colb = ni2 * 16 - h * 32 + 2 * tg;
#pragma unroll
                for (int mi = 0; mi < 2; ++mi) {
#pragma unroll
                    for (int t = 0; t < 2; ++t) {
                        const float p0 = exp2f(s[mi][t][0]);
                        const float p1 = exp2f(s[mi][t][1]);
                        const float p2 = exp2f(s[mi][t][2]);
                        const float p3 = exp2f(s[mi][t][3]);
                        lv[mi][0] += p0 + p1;
                        lv[mi][1] += p2 + p3;
                        *(__half2*)(Pw + (mi * 16 + g) * 40 + colb + t * 8) =
                            __floats2half2_rn(p0, p1);
                        *(__half2*)(Pw + (mi * 16 + g + 8) * 40 + colb + t * 8) =
                            __floats2half2_rn(p2, p3);
                    }
                }
            }
            __syncwarp();                      // P stores -> PV reads

            // ---- PV for this half (keys 32h..32h+31), 2 k16-steps ----
#pragma unroll
            for (int ksl = 0; ksl < 2; ++ksl) {
                uint32_t a[2][4];
#pragma unroll
                for (int mi = 0; mi < 2; ++mi)
                    ldsm4(a[mi][0], a[mi][1], a[mi][2], a[mi][3],
                          pwbase + mi * (16 * 80) + ksl * 32 + poff);
                uint32_t bfr[8][2];
#pragma unroll
                for (int ni2v = 0; ni2v < 4; ++ni2v)
                    ldsm4(bfr[2 * ni2v][0], bfr[2 * ni2v][1],
                          bfr[2 * ni2v + 1][0], bfr[2 * ni2v + 1][1],
                          vsb + ni2v * (16 * 144) + (h * 32 + ksl * 16) * 2);
#pragma unroll
                for (int ni = 0; ni < 8; ++ni) {
                    mma16(o[0][ni], a[0], bfr[ni]);
                    mma16(o[1][ni], a[1], bfr[ni]);
                }
            }
            __syncwarp();                      // PV reads done before P reuse
        }
    }

    // ---- final l reduction + epilogue: fp16 g_aoh ----
#pragma unroll
    for (int mi = 0; mi < 2; ++mi) {
#pragma unroll
        for (int off = 1; off <= 2; off <<= 1) {
            lv[mi][0] += __shfl_xor_sync(0xffffffffu, lv[mi][0], off);
            lv[mi][1] += __shfl_xor_sync(0xffffffffu, lv[mi][1], off);
        }
        const float inv0 = 1.0f / lv[mi][0];
        const float inv1 = 1.0f / lv[mi][1];
        const int rA = q0 + warp * 32 + mi * 16 + g;
        __half* aoA = g_aoh + ((size_t)b * NN + rA) * CC + h2 * DD;
        __half* aoB = g_aoh + ((size_t)b * NN + rA + 8) * CC + h2 * DD;
#pragma unroll
        for (int ni = 0; ni < 8; ++ni) {
            const int d = ni * 8 + 2 * tg;
            *(__half2*)(aoA + d) = __floats2half2_rn(o[mi][ni][0] * inv0, o[mi][ni][1] * inv0);
            *(__half2*)(aoB + d) = __floats2half2_rn(o[mi][ni][2] * inv1, o[mi][ni][3] * inv1);
        }
    }
}

// ---------------------------------------------------------------------------
extern "C" void kernel_launch(void* const* d_in, const int* in_sizes, int n_in,
                              void* d_out, int out_size)
{
    const float* x      = (const float*)d_in[0];
    const float* w_qkv  = (const float*)d_in[1];
    const float* w_proj = (const float*)d_in[2];
    const float* b_proj = (const float*)d_in[3];
    float* out = (float*)d_out;

    cudaFuncSetAttribute(gemm0_tc, cudaFuncAttributeMaxDynamicSharedMemorySize, GEMM_SMEM_BYTES);
    cudaFuncSetAttribute(gemm1_tc, cudaFuncAttributeMaxDynamicSharedMemorySize, GEMM_SMEM_BYTES);
    cudaFuncSetAttribute(attn_tc,  cudaFuncAttributeMaxDynamicSharedMemorySize, ATT_SMEM_BYTES);

    // 0) fused fp16 conversion of x, w_qkv, w_proj
    cvt_all<<<(N4_X + N4_WQ + N4_WP + 255) / 256, 256>>>(
        (const float4*)x, (const float4*)w_qkv, (const float4*)w_proj);

    // 1) QKV projection -> g_qh/g_kh (row) + g_vh (transposed)
    gemm0_tc<<<dim3(18, 64), 256, GEMM_SMEM_BYTES>>>();

    // 2) Flash attention per (q-chunk, head, batch)
    attn_tc<<<dim3(8, 12, 8), 128, ATT_SMEM_BYTES>>>();

    // 3) Output projection + bias -> fp32 out
    gemm1_tc<<<dim3(6, 64), 128, GEMM_SMEM_BYTES>>>(b_proj, out);
}